// round 4
// baseline (speedup 1.0000x reference)
#include <cuda_runtime.h>
#include <cuda_bf16.h>
#include <cstdint>

// Problem constants
#define BATCH 2
#define SEQ   2048
#define DIM   1024
#define HEADS 16
#define HDIM  64
#define MROWS (BATCH * SEQ)          // 4096
#define BH    (BATCH * HEADS)        // 32

// ---------------- scratch ----------------
__device__ float g_Q[(size_t)MROWS * DIM];
__device__ float g_K[(size_t)MROWS * DIM];
__device__ float g_V[(size_t)MROWS * DIM];
__device__ float g_O[(size_t)MROWS * DIM];

// ---------------- tf32 helpers ----------------
__device__ __forceinline__ uint32_t f2tf(float f) {
    uint32_t u;
    asm("cvt.rna.tf32.f32 %0, %1;" : "=r"(u) : "f"(f));
    return u;
}

__device__ __forceinline__ void mma_tf32(float c[4], const uint32_t a[4], const uint32_t b[2]) {
    asm volatile(
        "mma.sync.aligned.m16n8k8.row.col.f32.tf32.tf32.f32 "
        "{%0,%1,%2,%3}, {%4,%5,%6,%7}, {%8,%9}, {%0,%1,%2,%3};\n"
        : "+f"(c[0]), "+f"(c[1]), "+f"(c[2]), "+f"(c[3])
        : "r"(a[0]), "r"(a[1]), "r"(a[2]), "r"(a[3]), "r"(b[0]), "r"(b[1]));
}

// ---------------- pipelined tf32 GEMM: C = A @ Bsel^T (+bias) (+RoPE epilogue) ----------------
// A row-major [4096,1024]; B row-major [1024,1024] (weight W[n][k]); C row-major.
// Double-buffered smem, BK=16, one __syncthreads per k-iteration.
// blockIdx.z selects (B, C) among the three pointer slots (QKV); out-proj uses z=0 only.
#define BK   16
#define KSTR 20     // smem row stride (words): 20*g mod 32 distinct multiples of 4 -> +t conflict-free
#define ABUF (128 * KSTR)

template<bool ROPE, bool HAS_BIAS>
__global__ void __launch_bounds__(256, 2)
gemm_pipe(const float* __restrict__ A,
          const float* __restrict__ B0, const float* __restrict__ B1, const float* __restrict__ B2,
          float* __restrict__ C0, float* __restrict__ C1, float* __restrict__ C2,
          const float* __restrict__ bias,
          const float* __restrict__ cosb, const float* __restrict__ sinb)
{
    extern __shared__ uint32_t sm[];
    uint32_t* AsB = sm;              // 2 * ABUF
    uint32_t* BsB = sm + 2 * ABUF;   // 2 * ABUF

    const int z = blockIdx.z;
    const float* B = (z == 0) ? B0 : ((z == 1) ? B1 : B2);
    float*       C = (z == 0) ? C0 : ((z == 1) ? C1 : C2);

    const int m0 = blockIdx.y * 128;
    const int n0 = blockIdx.x * 128;

    const int tid  = threadIdx.x;
    const int warp = tid >> 5;
    const int lane = tid & 31;
    const int g    = lane >> 2;
    const int t    = lane & 3;
    const int wm   = warp >> 2;          // 0..1
    const int wn   = warp & 3;           // 0..3

    // staging-load mapping: thread -> (row = tid/2, col = (tid&1)*8), two float4 each
    const int lr = tid >> 1;
    const int lc = (tid & 1) * 8;
    const float* Aldg = &A[(size_t)(m0 + lr) * DIM + lc];
    const float* Bldg = &B[(size_t)(n0 + lr) * DIM + lc];

    float acc[4][4][4] = {};

    float4 ra0, ra1, rb0, rb1;

    // prologue: tile 0
    ra0 = *(const float4*)&Aldg[0];
    ra1 = *(const float4*)&Aldg[4];
    rb0 = *(const float4*)&Bldg[0];
    rb1 = *(const float4*)&Bldg[4];
    {
        uint4 pa0 = make_uint4(f2tf(ra0.x), f2tf(ra0.y), f2tf(ra0.z), f2tf(ra0.w));
        uint4 pa1 = make_uint4(f2tf(ra1.x), f2tf(ra1.y), f2tf(ra1.z), f2tf(ra1.w));
        uint4 pb0 = make_uint4(f2tf(rb0.x), f2tf(rb0.y), f2tf(rb0.z), f2tf(rb0.w));
        uint4 pb1 = make_uint4(f2tf(rb1.x), f2tf(rb1.y), f2tf(rb1.z), f2tf(rb1.w));
        *(uint4*)&AsB[lr * KSTR + lc]     = pa0;
        *(uint4*)&AsB[lr * KSTR + lc + 4] = pa1;
        *(uint4*)&BsB[lr * KSTR + lc]     = pb0;
        *(uint4*)&BsB[lr * KSTR + lc + 4] = pb1;
    }
    __syncthreads();

    const int NIT = DIM / BK;   // 64
    #pragma unroll 1
    for (int it = 0; it < NIT; it++) {
        const int cur = it & 1;
        const uint32_t* As = AsB + cur * ABUF;
        const uint32_t* Bs = BsB + cur * ABUF;

        // issue next tile's global loads early
        const bool more = (it + 1 < NIT);
        if (more) {
            const int k0 = (it + 1) * BK;
            ra0 = *(const float4*)&Aldg[k0];
            ra1 = *(const float4*)&Aldg[k0 + 4];
            rb0 = *(const float4*)&Bldg[k0];
            rb1 = *(const float4*)&Bldg[k0 + 4];
        }

        // compute: 2 k8 steps
        #pragma unroll
        for (int ks = 0; ks < 2; ks++) {
            const int k8 = ks * 8;
            uint32_t af[4][4];
            uint32_t bf[4][2];
            #pragma unroll
            for (int mf = 0; mf < 4; mf++) {
                int r = wm * 64 + mf * 16 + g;
                af[mf][0] = As[r * KSTR + k8 + t];
                af[mf][1] = As[(r + 8) * KSTR + k8 + t];
                af[mf][2] = As[r * KSTR + k8 + t + 4];
                af[mf][3] = As[(r + 8) * KSTR + k8 + t + 4];
            }
            #pragma unroll
            for (int nf = 0; nf < 4; nf++) {
                int c = wn * 32 + nf * 8 + g;
                bf[nf][0] = Bs[c * KSTR + k8 + t];
                bf[nf][1] = Bs[c * KSTR + k8 + t + 4];
            }
            #pragma unroll
            for (int mf = 0; mf < 4; mf++)
                #pragma unroll
                for (int nf = 0; nf < 4; nf++)
                    mma_tf32(acc[mf][nf], af[mf], bf[nf]);
        }

        // store next tile into the other buffer
        if (more) {
            uint32_t* Asn = AsB + (cur ^ 1) * ABUF;
            uint32_t* Bsn = BsB + (cur ^ 1) * ABUF;
            uint4 pa0 = make_uint4(f2tf(ra0.x), f2tf(ra0.y), f2tf(ra0.z), f2tf(ra0.w));
            uint4 pa1 = make_uint4(f2tf(ra1.x), f2tf(ra1.y), f2tf(ra1.z), f2tf(ra1.w));
            uint4 pb0 = make_uint4(f2tf(rb0.x), f2tf(rb0.y), f2tf(rb0.z), f2tf(rb0.w));
            uint4 pb1 = make_uint4(f2tf(rb1.x), f2tf(rb1.y), f2tf(rb1.z), f2tf(rb1.w));
            *(uint4*)&Asn[lr * KSTR + lc]     = pa0;
            *(uint4*)&Asn[lr * KSTR + lc + 4] = pa1;
            *(uint4*)&Bsn[lr * KSTR + lc]     = pb0;
            *(uint4*)&Bsn[lr * KSTR + lc + 4] = pb1;
        }
        __syncthreads();
    }

    // epilogue (optionally RoPE for z<2, optionally bias)
    const bool doRope = ROPE && (z < 2);
    #pragma unroll
    for (int mf = 0; mf < 4; mf++) {
        #pragma unroll
        for (int nf = 0; nf < 4; nf++) {
            int r = m0 + wm * 64 + mf * 16 + g;
            int c = n0 + wn * 32 + nf * 8 + 2 * t;
            float v00 = acc[mf][nf][0], v01 = acc[mf][nf][1];
            float v10 = acc[mf][nf][2], v11 = acc[mf][nf][3];
            if (doRope) {
                int i   = (c & 63) >> 1;
                int nA  = r & 2047;
                int nB  = (r + 8) & 2047;
                float cA = cosb[nA * 32 + i], sA = sinb[nA * 32 + i];
                float cB = cosb[nB * 32 + i], sB = sinb[nB * 32 + i];
                float o00 = v00 * cA - v01 * sA, o01 = v00 * sA + v01 * cA;
                float o10 = v10 * cB - v11 * sB, o11 = v10 * sB + v11 * cB;
                v00 = o00; v01 = o01; v10 = o10; v11 = o11;
            }
            if (HAS_BIAS) {
                v00 += bias[c]; v01 += bias[c + 1];
                v10 += bias[c]; v11 += bias[c + 1];
            }
            *(float2*)&C[(size_t)r       * DIM + c] = make_float2(v00, v01);
            *(float2*)&C[(size_t)(r + 8) * DIM + c] = make_float2(v10, v11);
        }
    }
}

// ---------------- fused flash attention ----------------
#define QS_STRIDE 68
#define KS_STRIDE 68
#define VS_STRIDE 72

__global__ void __launch_bounds__(256, 1)
flash_attn(const float* __restrict__ Q, const float* __restrict__ K,
           const float* __restrict__ V, float* __restrict__ O)
{
    extern __shared__ uint32_t sm[];
    uint32_t* Qs = sm;
    uint32_t* Ks = Qs + 128 * QS_STRIDE;
    uint32_t* Vs = Ks + 128 * KS_STRIDE;

    const int bh = blockIdx.y;
    const int b  = bh >> 4;
    const int h  = bh & 15;
    const int q0 = blockIdx.x * 128;

    const int tid  = threadIdx.x;
    const int warp = tid >> 5;
    const int lane = tid & 31;
    const int g    = lane >> 2;
    const int t    = lane & 3;
    const int wrow = warp * 16;

    const size_t base = ((size_t)b * SEQ) * DIM + (size_t)h * HDIM;

    #pragma unroll
    for (int i = tid; i < 128 * 16; i += 256) {
        int r = i >> 4, c4 = (i & 15) << 2;
        float4 v = *(const float4*)&Q[base + (size_t)(q0 + r) * DIM + c4];
        uint32_t* d = &Qs[r * QS_STRIDE + c4];
        d[0] = f2tf(v.x); d[1] = f2tf(v.y); d[2] = f2tf(v.z); d[3] = f2tf(v.w);
    }

    float m0 = -1e30f, m1 = -1e30f, l0 = 0.f, l1 = 0.f;
    float oacc[8][4] = {};

    for (int j0 = 0; j0 < SEQ; j0 += 128) {
        #pragma unroll
        for (int i = tid; i < 128 * 16; i += 256) {
            int r = i >> 4, c4 = (i & 15) << 2;
            float4 kv = *(const float4*)&K[base + (size_t)(j0 + r) * DIM + c4];
            uint32_t* kd = &Ks[r * KS_STRIDE + c4];
            kd[0] = f2tf(kv.x); kd[1] = f2tf(kv.y); kd[2] = f2tf(kv.z); kd[3] = f2tf(kv.w);
            float4 vv = *(const float4*)&V[base + (size_t)(j0 + r) * DIM + c4];
            uint32_t* vd = &Vs[r * VS_STRIDE + c4];
            vd[0] = f2tf(vv.x); vd[1] = f2tf(vv.y); vd[2] = f2tf(vv.z); vd[3] = f2tf(vv.w);
        }
        __syncthreads();

        float sacc[16][4];
        #pragma unroll
        for (int nf = 0; nf < 16; nf++)
            #pragma unroll
            for (int r = 0; r < 4; r++) sacc[nf][r] = 0.f;

        #pragma unroll
        for (int ks = 0; ks < 8; ks++) {
            const int k8 = ks * 8;
            uint32_t a[4];
            a[0] = Qs[(wrow + g    ) * QS_STRIDE + k8 + t    ];
            a[1] = Qs[(wrow + g + 8) * QS_STRIDE + k8 + t    ];
            a[2] = Qs[(wrow + g    ) * QS_STRIDE + k8 + t + 4];
            a[3] = Qs[(wrow + g + 8) * QS_STRIDE + k8 + t + 4];
            #pragma unroll
            for (int nf = 0; nf < 16; nf++) {
                uint32_t bb[2];
                bb[0] = Ks[(nf * 8 + g) * KS_STRIDE + k8 + t    ];
                bb[1] = Ks[(nf * 8 + g) * KS_STRIDE + k8 + t + 4];
                mma_tf32(sacc[nf], a, bb);
            }
        }

        float tm0 = -1e30f, tm1 = -1e30f;
        #pragma unroll
        for (int nf = 0; nf < 16; nf++) {
            #pragma unroll
            for (int r = 0; r < 4; r++) sacc[nf][r] *= 0.125f;
            tm0 = fmaxf(tm0, fmaxf(sacc[nf][0], sacc[nf][1]));
            tm1 = fmaxf(tm1, fmaxf(sacc[nf][2], sacc[nf][3]));
        }
        tm0 = fmaxf(tm0, __shfl_xor_sync(0xffffffffu, tm0, 1));
        tm0 = fmaxf(tm0, __shfl_xor_sync(0xffffffffu, tm0, 2));
        tm1 = fmaxf(tm1, __shfl_xor_sync(0xffffffffu, tm1, 1));
        tm1 = fmaxf(tm1, __shfl_xor_sync(0xffffffffu, tm1, 2));

        float nm0 = fmaxf(m0, tm0), nm1 = fmaxf(m1, tm1);
        float al0 = __expf(m0 - nm0), al1 = __expf(m1 - nm1);
        m0 = nm0; m1 = nm1;

        float rs0 = 0.f, rs1 = 0.f;
        uint32_t p[16][4];
        #pragma unroll
        for (int nf = 0; nf < 16; nf++) {
            float e0 = __expf(sacc[nf][0] - m0);
            float e1 = __expf(sacc[nf][1] - m0);
            float e2 = __expf(sacc[nf][2] - m1);
            float e3 = __expf(sacc[nf][3] - m1);
            rs0 += e0 + e1; rs1 += e2 + e3;
            p[nf][0] = f2tf(e0); p[nf][1] = f2tf(e1);
            p[nf][2] = f2tf(e2); p[nf][3] = f2tf(e3);
        }
        rs0 += __shfl_xor_sync(0xffffffffu, rs0, 1);
        rs0 += __shfl_xor_sync(0xffffffffu, rs0, 2);
        rs1 += __shfl_xor_sync(0xffffffffu, rs1, 1);
        rs1 += __shfl_xor_sync(0xffffffffu, rs1, 2);
        l0 = l0 * al0 + rs0;
        l1 = l1 * al1 + rs1;

        #pragma unroll
        for (int nf = 0; nf < 8; nf++) {
            oacc[nf][0] *= al0; oacc[nf][1] *= al0;
            oacc[nf][2] *= al1; oacc[nf][3] *= al1;
        }

        const int src0 = (g << 2) | (t >> 1);
        const int src1 = src0 + 2;
        const bool odd = (t & 1);
        #pragma unroll
        for (int ks = 0; ks < 16; ks++) {
            uint32_t x0 = __shfl_sync(0xffffffffu, p[ks][0], src0);
            uint32_t x1 = __shfl_sync(0xffffffffu, p[ks][1], src0);
            uint32_t x2 = __shfl_sync(0xffffffffu, p[ks][2], src0);
            uint32_t x3 = __shfl_sync(0xffffffffu, p[ks][3], src0);
            uint32_t y0 = __shfl_sync(0xffffffffu, p[ks][0], src1);
            uint32_t y1 = __shfl_sync(0xffffffffu, p[ks][1], src1);
            uint32_t y2 = __shfl_sync(0xffffffffu, p[ks][2], src1);
            uint32_t y3 = __shfl_sync(0xffffffffu, p[ks][3], src1);
            uint32_t a[4];
            a[0] = odd ? x1 : x0;
            a[1] = odd ? x3 : x2;
            a[2] = odd ? y1 : y0;
            a[3] = odd ? y3 : y2;
            const int k8 = ks * 8;
            #pragma unroll
            for (int nf = 0; nf < 8; nf++) {
                uint32_t bb[2];
                bb[0] = Vs[(k8 + t    ) * VS_STRIDE + nf * 8 + g];
                bb[1] = Vs[(k8 + t + 4) * VS_STRIDE + nf * 8 + g];
                mma_tf32(oacc[nf], a, bb);
            }
        }
        __syncthreads();
    }

    const float inv0 = 1.f / l0, inv1 = 1.f / l1;
    #pragma unroll
    for (int nf = 0; nf < 8; nf++) {
        int r0 = q0 + wrow + g;
        int c  = nf * 8 + 2 * t;
        float2 v0 = make_float2(oacc[nf][0] * inv0, oacc[nf][1] * inv0);
        float2 v1 = make_float2(oacc[nf][2] * inv1, oacc[nf][3] * inv1);
        *(float2*)&O[base + (size_t)r0 * DIM + c]       = v0;
        *(float2*)&O[base + (size_t)(r0 + 8) * DIM + c] = v1;
    }
}

// ---------------- launch ----------------
extern "C" void kernel_launch(void* const* d_in, const int* in_sizes, int n_in,
                              void* d_out, int out_size)
{
    const float* x   = (const float*)d_in[0];
    const float* fc  = (const float*)d_in[1];
    const float* fs  = (const float*)d_in[2];
    const float* Wq  = (const float*)d_in[3];
    const float* Wk  = (const float*)d_in[4];
    const float* Wv  = (const float*)d_in[5];
    const float* Wo  = (const float*)d_in[6];
    const float* bo  = (const float*)d_in[7];
    float* out = (float*)d_out;

    float *Q, *K, *V, *O;
    cudaGetSymbolAddress((void**)&Q, g_Q);
    cudaGetSymbolAddress((void**)&K, g_K);
    cudaGetSymbolAddress((void**)&V, g_V);
    cudaGetSymbolAddress((void**)&O, g_O);

    const int gemm_smem = 4 * ABUF * 4;   // 2 buffers x (A+B) x 128*20 words
    cudaFuncSetAttribute(gemm_pipe<true, false>,  cudaFuncAttributeMaxDynamicSharedMemorySize, gemm_smem);
    cudaFuncSetAttribute(gemm_pipe<false, true>,  cudaFuncAttributeMaxDynamicSharedMemorySize, gemm_smem);

    // 1) fused QKV projections + RoPE epilogue
    dim3 gQKV(DIM / 128, MROWS / 128, 3);
    gemm_pipe<true, false><<<gQKV, 256, gemm_smem>>>(
        x, Wq, Wk, Wv, Q, K, V, nullptr, fc, fs);

    // 2) fused attention
    const int fa_smem = (128 * QS_STRIDE + 128 * KS_STRIDE + 128 * VS_STRIDE) * 4;
    cudaFuncSetAttribute(flash_attn, cudaFuncAttributeMaxDynamicSharedMemorySize, fa_smem);
    dim3 gFA(SEQ / 128, BH, 1);
    flash_attn<<<gFA, 256, fa_smem>>>(Q, K, V, O);

    // 3) out = O @ Wo^T + bo
    dim3 gOut(DIM / 128, MROWS / 128, 1);
    gemm_pipe<false, true><<<gOut, 256, gemm_smem>>>(
        O, Wo, Wo, Wo, out, out, out, bo, nullptr, nullptr);
}

// round 7
// speedup vs baseline: 1.2237x; 1.2237x over previous
#include <cuda_runtime.h>
#include <cstdint>

// Problem constants
#define BATCH 2
#define SEQ   2048
#define DIM   1024
#define HEADS 16
#define HDIM  64
#define MROWS (BATCH * SEQ)          // 4096
#define BH    (BATCH * HEADS)        // 32

// ---------------- scratch ----------------
__device__ float g_X[(size_t)MROWS * DIM];        // rounded x
__device__ float g_W[(size_t)4 * DIM * DIM];      // rounded Wq,Wk,Wv,Wo
__device__ float g_Q[(size_t)MROWS * DIM];
__device__ float g_K[(size_t)MROWS * DIM];
__device__ float g_V[(size_t)MROWS * DIM];
__device__ float g_O[(size_t)MROWS * DIM];        // rounded by flash epilogue

// ---------------- helpers ----------------
__device__ __forceinline__ uint32_t f2tf(float f) {
    uint32_t u;
    asm("cvt.rna.tf32.f32 %0, %1;" : "=r"(u) : "f"(f));
    return u;
}

__device__ __forceinline__ void mma_tf32(float c[4], const uint32_t a[4], const uint32_t b[2]) {
    asm volatile(
        "mma.sync.aligned.m16n8k8.row.col.f32.tf32.tf32.f32 "
        "{%0,%1,%2,%3}, {%4,%5,%6,%7}, {%8,%9}, {%0,%1,%2,%3};\n"
        : "+f"(c[0]), "+f"(c[1]), "+f"(c[2]), "+f"(c[3])
        : "r"(a[0]), "r"(a[1]), "r"(a[2]), "r"(a[3]), "r"(b[0]), "r"(b[1]));
}

__device__ __forceinline__ void ldsm4(uint32_t r[4], uint32_t addr) {
    asm volatile("ldmatrix.sync.aligned.m8n8.x4.shared.b16 {%0,%1,%2,%3}, [%4];"
        : "=r"(r[0]), "=r"(r[1]), "=r"(r[2]), "=r"(r[3]) : "r"(addr));
}

__device__ __forceinline__ uint32_t smem_u32(const void* p) {
    uint32_t a;
    asm("{ .reg .u64 t; cvta.to.shared.u64 t, %1; cvt.u32.u64 %0, t; }" : "=r"(a) : "l"(p));
    return a;
}

#define CP_ASYNC16(dst, src) \
    asm volatile("cp.async.cg.shared.global [%0], [%1], 16;" :: "r"((uint32_t)(dst)), "l"(src) : "memory")
#define CP_COMMIT() asm volatile("cp.async.commit_group;" ::: "memory")

// ---------------- pre-pass: round x and weights to tf32 (rna) ----------------
__global__ void round_tf32_kernel(const float* __restrict__ x,
                                  const float* __restrict__ wq, const float* __restrict__ wk,
                                  const float* __restrict__ wv, const float* __restrict__ wo)
{
    const size_t i = (size_t)blockIdx.x * blockDim.x + threadIdx.x;   // float4 index, 2M total
    const float4* src;
    float4* dst;
    if (i < (1u << 20)) {
        src = (const float4*)x + i;
        dst = (float4*)g_X + i;
    } else {
        size_t j = i - (1u << 20);
        int w = (int)(j >> 18);
        const float* s = (w == 0) ? wq : ((w == 1) ? wk : ((w == 2) ? wv : wo));
        src = (const float4*)s + (j & 0x3FFFF);
        dst = (float4*)g_W + j;
    }
    float4 v = *src;
    float4 o;
    o.x = __uint_as_float(f2tf(v.x));
    o.y = __uint_as_float(f2tf(v.y));
    o.z = __uint_as_float(f2tf(v.z));
    o.w = __uint_as_float(f2tf(v.w));
    *dst = o;
}

// ---------------- ldmatrix + cp.async GEMM: C = A @ Wsel^T (+RoPE / +bias) ----------------
// A pre-rounded row-major [4096,1024]; W pre-rounded [n][k]; 128x128 tile, 256 threads.
#define KSTR  36                     // smem row stride in words (36*4=144B, 16B aligned, mod32=4)
#define OPW   (128 * KSTR)           // words per operand per stage = 4608
#define STGW  (2 * OPW)              // words per stage (A+B)      = 9216
#define G_SMEM (2 * STGW * 4)        // 73728 bytes

template<bool ROPE, bool HAS_BIAS>
__global__ void __launch_bounds__(256, 2)
gemm_ldsm(const float* __restrict__ A, const float* __restrict__ W,
          float* __restrict__ C0, float* __restrict__ C1, float* __restrict__ C2,
          const float* __restrict__ bias,
          const float* __restrict__ cosb, const float* __restrict__ sinb)
{
    extern __shared__ __align__(16) uint32_t sm[];
    const uint32_t sb = smem_u32(sm);

    const int z = blockIdx.z;
    const float* B = W + ((size_t)(ROPE ? z : 3) << 20);
    float* C = ROPE ? ((z == 0) ? C0 : ((z == 1) ? C1 : C2)) : C0;

    const int m0 = blockIdx.y * 128;
    const int n0 = blockIdx.x * 128;

    const int tid  = threadIdx.x;
    const int warp = tid >> 5;
    const int lane = tid & 31;
    const int g    = lane >> 2;
    const int t    = lane & 3;
    const int wm   = warp >> 2;          // 0..1
    const int wn   = warp & 3;           // 0..3

    // cp.async chunk mapping: 4 chunks of 16B per thread per operand
    int crow[4], ccol[4];
    #pragma unroll
    for (int j = 0; j < 4; j++) {
        int id = tid + 256 * j;          // 0..1023
        crow[j] = id >> 3;
        ccol[j] = (id & 7) * 4;          // float index
    }

    // ldmatrix per-lane base offsets
    const int rowA = ((lane >> 3) & 1) * 8 + (lane & 7);
    const int kcA  = (lane >> 4) * 4;
    const int rowB = ((lane >> 4) & 1) * 8 + (lane & 7);
    const int kcB  = ((lane >> 3) & 1) * 4;
    const uint32_t aBase = sb + (uint32_t)(((wm * 64 + rowA) * KSTR + kcA) * 4);
    const uint32_t bBase = sb + (uint32_t)((OPW + (wn * 32 + rowB) * KSTR + kcB) * 4);

    float acc[4][4][4] = {};

    const int NIT = DIM / 32;   // 32

    // fill stage for tile tt
    auto fill = [&](int tt) {
        const int s = tt & 1;
        const int k0 = tt * 32;
        const uint32_t stA = sb + (uint32_t)(s * STGW * 4);
        const uint32_t stB = stA + (uint32_t)(OPW * 4);
        #pragma unroll
        for (int j = 0; j < 4; j++) {
            CP_ASYNC16(stA + (uint32_t)((crow[j] * KSTR + ccol[j]) * 4),
                       &A[(size_t)(m0 + crow[j]) * DIM + k0 + ccol[j]]);
            CP_ASYNC16(stB + (uint32_t)((crow[j] * KSTR + ccol[j]) * 4),
                       &B[(size_t)(n0 + crow[j]) * DIM + k0 + ccol[j]]);
        }
        CP_COMMIT();
    };

    fill(0);

    #pragma unroll 1
    for (int it = 0; it < NIT; it++) {
        if (it + 1 < NIT) {
            fill(it + 1);
            asm volatile("cp.async.wait_group 1;" ::: "memory");
        } else {
            asm volatile("cp.async.wait_group 0;" ::: "memory");
        }
        __syncthreads();

        const uint32_t sOff = (uint32_t)((it & 1) * STGW * 4);
        const uint32_t aS = aBase + sOff;
        const uint32_t bS = bBase + sOff;

        #pragma unroll
        for (int ks = 0; ks < 4; ks++) {
            uint32_t af[4][4];
            #pragma unroll
            for (int mf = 0; mf < 4; mf++)
                ldsm4(af[mf], aS + (uint32_t)(mf * 16 * KSTR * 4 + ks * 32));
            uint32_t bf[4][2];
            #pragma unroll
            for (int p = 0; p < 2; p++) {
                uint32_t tmp[4];
                ldsm4(tmp, bS + (uint32_t)(p * 16 * KSTR * 4 + ks * 32));
                bf[2 * p][0]     = tmp[0]; bf[2 * p][1]     = tmp[1];
                bf[2 * p + 1][0] = tmp[2]; bf[2 * p + 1][1] = tmp[3];
            }
            #pragma unroll
            for (int mf = 0; mf < 4; mf++)
                #pragma unroll
                for (int nf = 0; nf < 4; nf++)
                    mma_tf32(acc[mf][nf], af[mf], bf[nf]);
        }
        __syncthreads();
    }

    // epilogue (optionally RoPE for z<2, optionally bias)
    const bool doRope = ROPE && (z < 2);
    #pragma unroll
    for (int mf = 0; mf < 4; mf++) {
        #pragma unroll
        for (int nf = 0; nf < 4; nf++) {
            int r = m0 + wm * 64 + mf * 16 + g;
            int c = n0 + wn * 32 + nf * 8 + 2 * t;
            float v00 = acc[mf][nf][0], v01 = acc[mf][nf][1];
            float v10 = acc[mf][nf][2], v11 = acc[mf][nf][3];
            if (doRope) {
                int i   = (c & 63) >> 1;
                int nA  = r & 2047;
                int nB  = (r + 8) & 2047;
                float cA = cosb[nA * 32 + i], sA = sinb[nA * 32 + i];
                float cB = cosb[nB * 32 + i], sB = sinb[nB * 32 + i];
                float o00 = v00 * cA - v01 * sA, o01 = v00 * sA + v01 * cA;
                float o10 = v10 * cB - v11 * sB, o11 = v10 * sB + v11 * cB;
                v00 = o00; v01 = o01; v10 = o10; v11 = o11;
            }
            if (HAS_BIAS) {
                v00 += bias[c]; v01 += bias[c + 1];
                v10 += bias[c]; v11 += bias[c + 1];
            }
            *(float2*)&C[(size_t)r       * DIM + c] = make_float2(v00, v01);
            *(float2*)&C[(size_t)(r + 8) * DIM + c] = make_float2(v10, v11);
        }
    }
}

// ---------------- fused flash attention (ldmatrix S-phase; O stored tf32-rounded) ----------------
#define QS_STRIDE 68
#define KS_STRIDE 68
#define VS_STRIDE 72

__global__ void __launch_bounds__(256, 1)
flash_attn(const float* __restrict__ Q, const float* __restrict__ K,
           const float* __restrict__ V, float* __restrict__ O)
{
    extern __shared__ uint32_t sm[];
    uint32_t* Qs = sm;
    uint32_t* Ks = Qs + 128 * QS_STRIDE;
    uint32_t* Vs = Ks + 128 * KS_STRIDE;
    const uint32_t sb  = smem_u32(sm);
    const uint32_t sbK = sb + 128 * QS_STRIDE * 4;

    const int bh = blockIdx.y;
    const int b  = bh >> 4;
    const int h  = bh & 15;
    const int q0 = blockIdx.x * 128;

    const int tid  = threadIdx.x;
    const int warp = tid >> 5;
    const int lane = tid & 31;
    const int g    = lane >> 2;
    const int t    = lane & 3;
    const int wrow = warp * 16;

    // ldmatrix lane offsets
    const int rowA = ((lane >> 3) & 1) * 8 + (lane & 7);
    const int kcA  = (lane >> 4) * 4;
    const int rowB = ((lane >> 4) & 1) * 8 + (lane & 7);
    const int kcB  = ((lane >> 3) & 1) * 4;
    const uint32_t qAddr = sb  + (uint32_t)(((wrow + rowA) * QS_STRIDE + kcA) * 4);
    const uint32_t kAddr = sbK + (uint32_t)((rowB * KS_STRIDE + kcB) * 4);

    const size_t base = ((size_t)b * SEQ) * DIM + (size_t)h * HDIM;

    #pragma unroll
    for (int i = tid; i < 128 * 16; i += 256) {
        int r = i >> 4, c4 = (i & 15) << 2;
        float4 v = *(const float4*)&Q[base + (size_t)(q0 + r) * DIM + c4];
        uint32_t* d = &Qs[r * QS_STRIDE + c4];
        d[0] = f2tf(v.x); d[1] = f2tf(v.y); d[2] = f2tf(v.z); d[3] = f2tf(v.w);
    }

    float m0 = -1e30f, m1 = -1e30f, l0 = 0.f, l1 = 0.f;
    float oacc[8][4] = {};

    for (int j0 = 0; j0 < SEQ; j0 += 128) {
        #pragma unroll
        for (int i = tid; i < 128 * 16; i += 256) {
            int r = i >> 4, c4 = (i & 15) << 2;
            float4 kv = *(const float4*)&K[base + (size_t)(j0 + r) * DIM + c4];
            uint32_t* kd = &Ks[r * KS_STRIDE + c4];
            kd[0] = f2tf(kv.x); kd[1] = f2tf(kv.y); kd[2] = f2tf(kv.z); kd[3] = f2tf(kv.w);
            float4 vv = *(const float4*)&V[base + (size_t)(j0 + r) * DIM + c4];
            uint32_t* vd = &Vs[r * VS_STRIDE + c4];
            vd[0] = f2tf(vv.x); vd[1] = f2tf(vv.y); vd[2] = f2tf(vv.z); vd[3] = f2tf(vv.w);
        }
        __syncthreads();

        // ---- S = Q @ K^T via ldmatrix fragments ----
        float sacc[16][4];
        #pragma unroll
        for (int nf = 0; nf < 16; nf++)
            #pragma unroll
            for (int r = 0; r < 4; r++) sacc[nf][r] = 0.f;

        #pragma unroll
        for (int ks = 0; ks < 8; ks++) {
            uint32_t a[4];
            ldsm4(a, qAddr + ks * 32);
            #pragma unroll
            for (int p = 0; p < 8; p++) {
                uint32_t tmp[4];
                ldsm4(tmp, kAddr + (uint32_t)(p * 16 * KS_STRIDE * 4 + ks * 32));
                uint32_t b0[2] = {tmp[0], tmp[1]};
                uint32_t b1[2] = {tmp[2], tmp[3]};
                mma_tf32(sacc[2 * p],     a, b0);
                mma_tf32(sacc[2 * p + 1], a, b1);
            }
        }

        // ---- online softmax ----
        float tm0 = -1e30f, tm1 = -1e30f;
        #pragma unroll
        for (int nf = 0; nf < 16; nf++) {
            #pragma unroll
            for (int r = 0; r < 4; r++) sacc[nf][r] *= 0.125f;
            tm0 = fmaxf(tm0, fmaxf(sacc[nf][0], sacc[nf][1]));
            tm1 = fmaxf(tm1, fmaxf(sacc[nf][2], sacc[nf][3]));
        }
        tm0 = fmaxf(tm0, __shfl_xor_sync(0xffffffffu, tm0, 1));
        tm0 = fmaxf(tm0, __shfl_xor_sync(0xffffffffu, tm0, 2));
        tm1 = fmaxf(tm1, __shfl_xor_sync(0xffffffffu, tm1, 1));
        tm1 = fmaxf(tm1, __shfl_xor_sync(0xffffffffu, tm1, 2));

        float nm0 = fmaxf(m0, tm0), nm1 = fmaxf(m1, tm1);
        float al0 = __expf(m0 - nm0), al1 = __expf(m1 - nm1);
        m0 = nm0; m1 = nm1;

        float rs0 = 0.f, rs1 = 0.f;
        uint32_t p[16][4];
        #pragma unroll
        for (int nf = 0; nf < 16; nf++) {
            float e0 = __expf(sacc[nf][0] - m0);
            float e1 = __expf(sacc[nf][1] - m0);
            float e2 = __expf(sacc[nf][2] - m1);
            float e3 = __expf(sacc[nf][3] - m1);
            rs0 += e0 + e1; rs1 += e2 + e3;
            p[nf][0] = f2tf(e0); p[nf][1] = f2tf(e1);
            p[nf][2] = f2tf(e2); p[nf][3] = f2tf(e3);
        }
        rs0 += __shfl_xor_sync(0xffffffffu, rs0, 1);
        rs0 += __shfl_xor_sync(0xffffffffu, rs0, 2);
        rs1 += __shfl_xor_sync(0xffffffffu, rs1, 1);
        rs1 += __shfl_xor_sync(0xffffffffu, rs1, 2);
        l0 = l0 * al0 + rs0;
        l1 = l1 * al1 + rs1;

        #pragma unroll
        for (int nf = 0; nf < 8; nf++) {
            oacc[nf][0] *= al0; oacc[nf][1] *= al0;
            oacc[nf][2] *= al1; oacc[nf][3] *= al1;
        }

        // ---- O += P @ V  (P in registers; V scalar LDS, conflict-free) ----
        const int src0 = (g << 2) | (t >> 1);
        const int src1 = src0 + 2;
        const bool odd = (t & 1);
        #pragma unroll
        for (int ks = 0; ks < 16; ks++) {
            uint32_t x0 = __shfl_sync(0xffffffffu, p[ks][0], src0);
            uint32_t x1 = __shfl_sync(0xffffffffu, p[ks][1], src0);
            uint32_t x2 = __shfl_sync(0xffffffffu, p[ks][2], src0);
            uint32_t x3 = __shfl_sync(0xffffffffu, p[ks][3], src0);
            uint32_t y0 = __shfl_sync(0xffffffffu, p[ks][0], src1);
            uint32_t y1 = __shfl_sync(0xffffffffu, p[ks][1], src1);
            uint32_t y2 = __shfl_sync(0xffffffffu, p[ks][2], src1);
            uint32_t y3 = __shfl_sync(0xffffffffu, p[ks][3], src1);
            uint32_t a[4];
            a[0] = odd ? x1 : x0;
            a[1] = odd ? x3 : x2;
            a[2] = odd ? y1 : y0;
            a[3] = odd ? y3 : y2;
            const int k8 = ks * 8;
            #pragma unroll
            for (int nf = 0; nf < 8; nf++) {
                uint32_t bb[2];
                bb[0] = Vs[(k8 + t    ) * VS_STRIDE + nf * 8 + g];
                bb[1] = Vs[(k8 + t + 4) * VS_STRIDE + nf * 8 + g];
                mma_tf32(oacc[nf], a, bb);
            }
        }
        __syncthreads();
    }

    const float inv0 = 1.f / l0, inv1 = 1.f / l1;
    #pragma unroll
    for (int nf = 0; nf < 8; nf++) {
        int r0 = q0 + wrow + g;
        int c  = nf * 8 + 2 * t;
        float2 v0 = make_float2(__uint_as_float(f2tf(oacc[nf][0] * inv0)),
                                __uint_as_float(f2tf(oacc[nf][1] * inv0)));
        float2 v1 = make_float2(__uint_as_float(f2tf(oacc[nf][2] * inv1)),
                                __uint_as_float(f2tf(oacc[nf][3] * inv1)));
        *(float2*)&O[base + (size_t)r0 * DIM + c]       = v0;
        *(float2*)&O[base + (size_t)(r0 + 8) * DIM + c] = v1;
    }
}

// ---------------- launch ----------------
extern "C" void kernel_launch(void* const* d_in, const int* in_sizes, int n_in,
                              void* d_out, int out_size)
{
    const float* x   = (const float*)d_in[0];
    const float* fc  = (const float*)d_in[1];
    const float* fs  = (const float*)d_in[2];
    const float* Wq  = (const float*)d_in[3];
    const float* Wk  = (const float*)d_in[4];
    const float* Wv  = (const float*)d_in[5];
    const float* Wo  = (const float*)d_in[6];
    const float* bo  = (const float*)d_in[7];
    float* out = (float*)d_out;

    float *X, *W, *Q, *K, *V, *O;
    cudaGetSymbolAddress((void**)&X, g_X);
    cudaGetSymbolAddress((void**)&W, g_W);
    cudaGetSymbolAddress((void**)&Q, g_Q);
    cudaGetSymbolAddress((void**)&K, g_K);
    cudaGetSymbolAddress((void**)&V, g_V);
    cudaGetSymbolAddress((void**)&O, g_O);

    // 0) pre-round x and weights
    round_tf32_kernel<<<8192, 256>>>(x, Wq, Wk, Wv, Wo);

    // 1) fused QKV projections + RoPE epilogue
    cudaFuncSetAttribute(gemm_ldsm<true, false>,  cudaFuncAttributeMaxDynamicSharedMemorySize, G_SMEM);
    cudaFuncSetAttribute(gemm_ldsm<false, true>,  cudaFuncAttributeMaxDynamicSharedMemorySize, G_SMEM);
    dim3 gQKV(DIM / 128, MROWS / 128, 3);
    gemm_ldsm<true, false><<<gQKV, 256, G_SMEM>>>(X, W, Q, K, V, nullptr, fc, fs);

    // 2) fused attention (writes rounded O)
    const int fa_smem = (128 * QS_STRIDE + 128 * KS_STRIDE + 128 * VS_STRIDE) * 4;
    cudaFuncSetAttribute(flash_attn, cudaFuncAttributeMaxDynamicSharedMemorySize, fa_smem);
    dim3 gFA(SEQ / 128, BH, 1);
    flash_attn<<<gFA, 256, fa_smem>>>(Q, K, V, O);

    // 3) out = O @ Wo^T + bo
    dim3 gOut(DIM / 128, MROWS / 128, 1);
    gemm_ldsm<false, true><<<gOut, 256, G_SMEM>>>(O, W, out, out, out, bo, nullptr, nullptr);
}

// round 8
// speedup vs baseline: 2.4547x; 2.0059x over previous
#include <cuda_runtime.h>
#include <cuda_fp16.h>
#include <cstdint>

// Problem constants
#define BATCH 2
#define SEQ   2048
#define DIM   1024
#define HEADS 16
#define HDIM  64
#define MROWS (BATCH * SEQ)          // 4096
#define BH    (BATCH * HEADS)        // 32

// ---------------- scratch (half operand buffers) ----------------
__device__ __half g_Xh[(size_t)MROWS * DIM];
__device__ __half g_Wh[(size_t)4 * DIM * DIM];
__device__ __half g_Qh[(size_t)MROWS * DIM];
__device__ __half g_Kh[(size_t)MROWS * DIM];
__device__ __half g_Vh[(size_t)MROWS * DIM];
__device__ __half g_Oh[(size_t)MROWS * DIM];

// ---------------- helpers ----------------
__device__ __forceinline__ uint32_t f2h2(float lo, float hi) {
    __half2 h = __floats2half2_rn(lo, hi);
    return *(uint32_t*)&h;
}

__device__ __forceinline__ void mma_f16(float c[4], const uint32_t a[4], const uint32_t b[2]) {
    asm volatile(
        "mma.sync.aligned.m16n8k16.row.col.f32.f16.f16.f32 "
        "{%0,%1,%2,%3}, {%4,%5,%6,%7}, {%8,%9}, {%0,%1,%2,%3};\n"
        : "+f"(c[0]), "+f"(c[1]), "+f"(c[2]), "+f"(c[3])
        : "r"(a[0]), "r"(a[1]), "r"(a[2]), "r"(a[3]), "r"(b[0]), "r"(b[1]));
}

__device__ __forceinline__ void ldsm4(uint32_t r[4], uint32_t addr) {
    asm volatile("ldmatrix.sync.aligned.m8n8.x4.shared.b16 {%0,%1,%2,%3}, [%4];"
        : "=r"(r[0]), "=r"(r[1]), "=r"(r[2]), "=r"(r[3]) : "r"(addr));
}

__device__ __forceinline__ void ldsm4t(uint32_t r[4], uint32_t addr) {
    asm volatile("ldmatrix.sync.aligned.m8n8.x4.trans.shared.b16 {%0,%1,%2,%3}, [%4];"
        : "=r"(r[0]), "=r"(r[1]), "=r"(r[2]), "=r"(r[3]) : "r"(addr));
}

__device__ __forceinline__ uint32_t smem_u32(const void* p) {
    uint32_t a;
    asm("{ .reg .u64 t; cvta.to.shared.u64 t, %1; cvt.u32.u64 %0, t; }" : "=r"(a) : "l"(p));
    return a;
}

#define CP_ASYNC16(dst, src) \
    asm volatile("cp.async.cg.shared.global [%0], [%1], 16;" :: "r"((uint32_t)(dst)), "l"(src) : "memory")
#define CP_COMMIT() asm volatile("cp.async.commit_group;" ::: "memory")

// ---------------- pre-pass: convert x and weights to half ----------------
__global__ void to_half_kernel(const float* __restrict__ x,
                               const float* __restrict__ wq, const float* __restrict__ wk,
                               const float* __restrict__ wv, const float* __restrict__ wo)
{
    const size_t i = (size_t)blockIdx.x * blockDim.x + threadIdx.x;   // float4 index, 2M total
    const float4* src;
    uint2* dst;
    if (i < (1u << 20)) {
        src = (const float4*)x + i;
        dst = (uint2*)g_Xh + i;
    } else {
        size_t j = i - (1u << 20);
        int w = (int)(j >> 18);
        const float* s = (w == 0) ? wq : ((w == 1) ? wk : ((w == 2) ? wv : wo));
        src = (const float4*)s + (j & 0x3FFFF);
        dst = (uint2*)g_Wh + j;
    }
    float4 v = *src;
    *dst = make_uint2(f2h2(v.x, v.y), f2h2(v.z, v.w));
}

// ---------------- fp16 ldmatrix + cp.async GEMM ----------------
// A half row-major [4096,1024]; W half [n][k]; 128x128 tile, 256 threads, BK=64.
// Smem row: 64 halfs data + 8 pad = 72 halfs = 144 bytes.
#define RSTR   144                    // row stride bytes
#define OPB    (128 * RSTR)           // bytes per operand per stage = 18432
#define STGB   (2 * OPB)              // bytes per stage             = 36864
#define G_SMEM (2 * STGB)             // 73728

template<bool QKV>
__global__ void __launch_bounds__(256, 2)
gemm_h(const __half* __restrict__ A, const __half* __restrict__ W,
       __half* __restrict__ C0h, __half* __restrict__ C1h, __half* __restrict__ C2h,
       float* __restrict__ Cf, const float* __restrict__ bias,
       const float* __restrict__ cosb, const float* __restrict__ sinb)
{
    extern __shared__ __align__(16) char sm[];
    const uint32_t sb = smem_u32(sm);

    const int z = blockIdx.z;
    const __half* B = W + ((size_t)(QKV ? z : 3) << 20);

    const int m0 = blockIdx.y * 128;
    const int n0 = blockIdx.x * 128;

    const int tid  = threadIdx.x;
    const int warp = tid >> 5;
    const int lane = tid & 31;
    const int g    = lane >> 2;
    const int t    = lane & 3;
    const int wm   = warp >> 2;          // 0..1
    const int wn   = warp & 3;           // 0..3

    // cp.async chunk mapping: 4 chunks of 16B (8 halfs) per thread per operand
    int crow[4], cch[4];
    #pragma unroll
    for (int j = 0; j < 4; j++) {
        int id = tid + 256 * j;          // 0..1023
        crow[j] = id >> 3;
        cch[j]  = id & 7;
    }

    // ldmatrix per-lane base offsets (bytes)
    const uint32_t aBase = sb + (uint32_t)((wm * 64 + ((lane >> 3) & 1) * 8 + (lane & 7)) * RSTR
                                           + (lane >> 4) * 16);
    const uint32_t bBase = sb + (uint32_t)OPB
                         + (uint32_t)((wn * 32 + ((lane >> 4) & 1) * 8 + (lane & 7)) * RSTR
                                      + ((lane >> 3) & 1) * 16);

    float acc[4][4][4] = {};

    const int NIT = DIM / 64;   // 16

    auto fill = [&](int tt) {
        const int s  = tt & 1;
        const int k0 = tt * 64;                 // half index
        const uint32_t stA = sb + (uint32_t)(s * STGB);
        const uint32_t stB = stA + (uint32_t)OPB;
        #pragma unroll
        for (int j = 0; j < 4; j++) {
            CP_ASYNC16(stA + (uint32_t)(crow[j] * RSTR + cch[j] * 16),
                       &A[(size_t)(m0 + crow[j]) * DIM + k0 + cch[j] * 8]);
            CP_ASYNC16(stB + (uint32_t)(crow[j] * RSTR + cch[j] * 16),
                       &B[(size_t)(n0 + crow[j]) * DIM + k0 + cch[j] * 8]);
        }
        CP_COMMIT();
    };

    fill(0);

    #pragma unroll 1
    for (int it = 0; it < NIT; it++) {
        if (it + 1 < NIT) {
            fill(it + 1);
            asm volatile("cp.async.wait_group 1;" ::: "memory");
        } else {
            asm volatile("cp.async.wait_group 0;" ::: "memory");
        }
        __syncthreads();

        const uint32_t sOff = (uint32_t)((it & 1) * STGB);
        const uint32_t aS = aBase + sOff;
        const uint32_t bS = bBase + sOff;

        #pragma unroll
        for (int ks = 0; ks < 4; ks++) {        // 4 k16-steps per BK=64 tile
            uint32_t af[4][4];
            #pragma unroll
            for (int mf = 0; mf < 4; mf++)
                ldsm4(af[mf], aS + (uint32_t)(mf * 16 * RSTR + ks * 32));
            uint32_t bf[4][2];
            #pragma unroll
            for (int p = 0; p < 2; p++) {
                uint32_t tmp[4];
                ldsm4(tmp, bS + (uint32_t)(p * 16 * RSTR + ks * 32));
                bf[2 * p][0]     = tmp[0]; bf[2 * p][1]     = tmp[1];
                bf[2 * p + 1][0] = tmp[2]; bf[2 * p + 1][1] = tmp[3];
            }
            #pragma unroll
            for (int mf = 0; mf < 4; mf++)
                #pragma unroll
                for (int nf = 0; nf < 4; nf++)
                    mma_f16(acc[mf][nf], af[mf], bf[nf]);
        }
        __syncthreads();
    }

    // epilogue
    #pragma unroll
    for (int mf = 0; mf < 4; mf++) {
        #pragma unroll
        for (int nf = 0; nf < 4; nf++) {
            int r = m0 + wm * 64 + mf * 16 + g;
            int c = n0 + wn * 32 + nf * 8 + 2 * t;
            float v00 = acc[mf][nf][0], v01 = acc[mf][nf][1];
            float v10 = acc[mf][nf][2], v11 = acc[mf][nf][3];
            if (QKV) {
                __half* C = (z == 0) ? C0h : ((z == 1) ? C1h : C2h);
                if (z < 2) {   // RoPE on Q,K; fold 1/8 attn scale into Q
                    int i  = (c & 63) >> 1;
                    int nA = r & 2047, nB = (r + 8) & 2047;
                    float cA = cosb[nA * 32 + i], sA = sinb[nA * 32 + i];
                    float cB = cosb[nB * 32 + i], sB = sinb[nB * 32 + i];
                    float o00 = v00 * cA - v01 * sA, o01 = v00 * sA + v01 * cA;
                    float o10 = v10 * cB - v11 * sB, o11 = v10 * sB + v11 * cB;
                    if (z == 0) { o00 *= 0.125f; o01 *= 0.125f; o10 *= 0.125f; o11 *= 0.125f; }
                    v00 = o00; v01 = o01; v10 = o10; v11 = o11;
                }
                *(uint32_t*)&C[(size_t)r       * DIM + c] = f2h2(v00, v01);
                *(uint32_t*)&C[(size_t)(r + 8) * DIM + c] = f2h2(v10, v11);
            } else {
                float b0 = bias[c], b1 = bias[c + 1];
                *(float2*)&Cf[(size_t)r       * DIM + c] = make_float2(v00 + b0, v01 + b1);
                *(float2*)&Cf[(size_t)(r + 8) * DIM + c] = make_float2(v10 + b0, v11 + b1);
            }
        }
    }
}

// ---------------- fp16 fused flash attention ----------------
// smem: Qs [128 x 72 halfs], Ks same, Vs [key 128 x 72 halfs]; 144B rows.
#define FA_Q 0
#define FA_K 18432
#define FA_V 36864
#define FA_SMEM 55296

__global__ void __launch_bounds__(256, 2)
flash_attn(const __half* __restrict__ Q, const __half* __restrict__ K,
           const __half* __restrict__ V, __half* __restrict__ O)
{
    extern __shared__ __align__(16) char sm[];
    const uint32_t sb = smem_u32(sm);

    const int bh = blockIdx.y;
    const int b  = bh >> 4;
    const int h  = bh & 15;
    const int q0 = blockIdx.x * 128;

    const int tid  = threadIdx.x;
    const int warp = tid >> 5;
    const int lane = tid & 31;
    const int g    = lane >> 2;
    const int t    = lane & 3;
    const int wrow = warp * 16;

    const size_t hoff = (size_t)h * HDIM;
    const size_t tok0 = (size_t)b * SEQ;

    // staging chunks: 4 per thread (128 rows x 8 chunks of 8 halfs)
    int crow[4], cch[4];
    #pragma unroll
    for (int j = 0; j < 4; j++) {
        int id = tid + 256 * j;
        crow[j] = id >> 3;
        cch[j]  = id & 7;
    }

    // ldmatrix lane offsets (bytes)
    const uint32_t qAddr = sb + FA_Q + (uint32_t)((wrow + ((lane >> 3) & 1) * 8 + (lane & 7)) * RSTR
                                                  + (lane >> 4) * 16);
    const uint32_t kAddr = sb + FA_K + (uint32_t)((((lane >> 4) & 1) * 8 + (lane & 7)) * RSTR
                                                  + ((lane >> 3) & 1) * 16);
    const uint32_t vAddr = sb + FA_V + (uint32_t)((((lane >> 3) & 1) * 8 + (lane & 7)) * RSTR
                                                  + ((lane >> 4) & 1) * 16);

    // stage Q tile
    #pragma unroll
    for (int j = 0; j < 4; j++)
        CP_ASYNC16(sb + FA_Q + (uint32_t)(crow[j] * RSTR + cch[j] * 16),
                   &Q[(tok0 + q0 + crow[j]) * DIM + hoff + cch[j] * 8]);
    CP_COMMIT();

    float m0 = -1e30f, m1 = -1e30f, l0 = 0.f, l1 = 0.f;
    float oacc[8][4] = {};

    #pragma unroll 1
    for (int j0 = 0; j0 < SEQ; j0 += 128) {
        // stage K,V tiles
        #pragma unroll
        for (int j = 0; j < 4; j++) {
            CP_ASYNC16(sb + FA_K + (uint32_t)(crow[j] * RSTR + cch[j] * 16),
                       &K[(tok0 + j0 + crow[j]) * DIM + hoff + cch[j] * 8]);
            CP_ASYNC16(sb + FA_V + (uint32_t)(crow[j] * RSTR + cch[j] * 16),
                       &V[(tok0 + j0 + crow[j]) * DIM + hoff + cch[j] * 8]);
        }
        CP_COMMIT();
        asm volatile("cp.async.wait_group 0;" ::: "memory");
        __syncthreads();

        // ---- S = Q @ K^T (fp16 inputs, fp32 accum); Q pre-scaled by 1/8 ----
        float sacc[16][4];
        #pragma unroll
        for (int nf = 0; nf < 16; nf++)
            #pragma unroll
            for (int r = 0; r < 4; r++) sacc[nf][r] = 0.f;

        #pragma unroll
        for (int ks = 0; ks < 4; ks++) {        // 4 k16-steps over d=64
            uint32_t a[4];
            ldsm4(a, qAddr + (uint32_t)(ks * 32));
            #pragma unroll
            for (int p = 0; p < 8; p++) {       // 16 key-tiles (pairs)
                uint32_t tmp[4];
                ldsm4(tmp, kAddr + (uint32_t)(p * 16 * RSTR + ks * 32));
                uint32_t b0[2] = {tmp[0], tmp[1]};
                uint32_t b1[2] = {tmp[2], tmp[3]};
                mma_f16(sacc[2 * p],     a, b0);
                mma_f16(sacc[2 * p + 1], a, b1);
            }
        }

        // ---- online softmax ----
        float tm0 = -1e30f, tm1 = -1e30f;
        #pragma unroll
        for (int nf = 0; nf < 16; nf++) {
            tm0 = fmaxf(tm0, fmaxf(sacc[nf][0], sacc[nf][1]));
            tm1 = fmaxf(tm1, fmaxf(sacc[nf][2], sacc[nf][3]));
        }
        tm0 = fmaxf(tm0, __shfl_xor_sync(0xffffffffu, tm0, 1));
        tm0 = fmaxf(tm0, __shfl_xor_sync(0xffffffffu, tm0, 2));
        tm1 = fmaxf(tm1, __shfl_xor_sync(0xffffffffu, tm1, 1));
        tm1 = fmaxf(tm1, __shfl_xor_sync(0xffffffffu, tm1, 2));

        float nm0 = fmaxf(m0, tm0), nm1 = fmaxf(m1, tm1);
        float al0 = __expf(m0 - nm0), al1 = __expf(m1 - nm1);
        m0 = nm0; m1 = nm1;

        float rs0 = 0.f, rs1 = 0.f;
        uint32_t ph[16][2];          // half2-packed P, already in PV A-fragment layout
        #pragma unroll
        for (int nf = 0; nf < 16; nf++) {
            float e0 = __expf(sacc[nf][0] - m0);
            float e1 = __expf(sacc[nf][1] - m0);
            float e2 = __expf(sacc[nf][2] - m1);
            float e3 = __expf(sacc[nf][3] - m1);
            rs0 += e0 + e1; rs1 += e2 + e3;
            ph[nf][0] = f2h2(e0, e1);
            ph[nf][1] = f2h2(e2, e3);
        }
        rs0 += __shfl_xor_sync(0xffffffffu, rs0, 1);
        rs0 += __shfl_xor_sync(0xffffffffu, rs0, 2);
        rs1 += __shfl_xor_sync(0xffffffffu, rs1, 1);
        rs1 += __shfl_xor_sync(0xffffffffu, rs1, 2);
        l0 = l0 * al0 + rs0;
        l1 = l1 * al1 + rs1;

        #pragma unroll
        for (int nf = 0; nf < 8; nf++) {
            oacc[nf][0] *= al0; oacc[nf][1] *= al0;
            oacc[nf][2] *= al1; oacc[nf][3] *= al1;
        }

        // ---- O += P @ V (V^T fragments via ldmatrix.trans) ----
        #pragma unroll
        for (int ks = 0; ks < 8; ks++) {        // 8 k16-steps over 128 keys
            uint32_t a[4] = {ph[2 * ks][0], ph[2 * ks][1], ph[2 * ks + 1][0], ph[2 * ks + 1][1]};
            const uint32_t vk = vAddr + (uint32_t)(ks * 16 * RSTR);
            #pragma unroll
            for (int dt = 0; dt < 4; dt++) {    // 4 d-tile pairs (d = 64)
                uint32_t tmp[4];
                ldsm4t(tmp, vk + (uint32_t)(dt * 32));
                uint32_t b0[2] = {tmp[0], tmp[1]};
                uint32_t b1[2] = {tmp[2], tmp[3]};
                mma_f16(oacc[2 * dt],     a, b0);
                mma_f16(oacc[2 * dt + 1], a, b1);
            }
        }
        __syncthreads();
    }

    // ---- finalize ----
    const float inv0 = 1.f / l0, inv1 = 1.f / l1;
    #pragma unroll
    for (int nf = 0; nf < 8; nf++) {
        int r0 = q0 + wrow + g;
        int c  = nf * 8 + 2 * t;
        *(uint32_t*)&O[(tok0 + r0) * DIM + hoff + c]       = f2h2(oacc[nf][0] * inv0, oacc[nf][1] * inv0);
        *(uint32_t*)&O[(tok0 + r0 + 8) * DIM + hoff + c]   = f2h2(oacc[nf][2] * inv1, oacc[nf][3] * inv1);
    }
}

// ---------------- launch ----------------
extern "C" void kernel_launch(void* const* d_in, const int* in_sizes, int n_in,
                              void* d_out, int out_size)
{
    const float* x   = (const float*)d_in[0];
    const float* fc  = (const float*)d_in[1];
    const float* fs  = (const float*)d_in[2];
    const float* Wq  = (const float*)d_in[3];
    const float* Wk  = (const float*)d_in[4];
    const float* Wv  = (const float*)d_in[5];
    const float* Wo  = (const float*)d_in[6];
    const float* bo  = (const float*)d_in[7];
    float* out = (float*)d_out;

    __half *Xh, *Wh, *Qh, *Kh, *Vh, *Oh;
    cudaGetSymbolAddress((void**)&Xh, g_Xh);
    cudaGetSymbolAddress((void**)&Wh, g_Wh);
    cudaGetSymbolAddress((void**)&Qh, g_Qh);
    cudaGetSymbolAddress((void**)&Kh, g_Kh);
    cudaGetSymbolAddress((void**)&Vh, g_Vh);
    cudaGetSymbolAddress((void**)&Oh, g_Oh);

    // 0) convert inputs to half
    to_half_kernel<<<8192, 256>>>(x, Wq, Wk, Wv, Wo);

    // 1) fused QKV projections + RoPE (+1/8 scale on Q) epilogue
    cudaFuncSetAttribute(gemm_h<true>,  cudaFuncAttributeMaxDynamicSharedMemorySize, G_SMEM);
    cudaFuncSetAttribute(gemm_h<false>, cudaFuncAttributeMaxDynamicSharedMemorySize, G_SMEM);
    dim3 gQKV(DIM / 128, MROWS / 128, 3);
    gemm_h<true><<<gQKV, 256, G_SMEM>>>(Xh, Wh, Qh, Kh, Vh, nullptr, nullptr, fc, fs);

    // 2) fused attention (writes half O)
    cudaFuncSetAttribute(flash_attn, cudaFuncAttributeMaxDynamicSharedMemorySize, FA_SMEM);
    dim3 gFA(SEQ / 128, BH, 1);
    flash_attn<<<gFA, 256, FA_SMEM>>>(Qh, Kh, Vh, Oh);

    // 3) out = O @ Wo^T + bo
    dim3 gOut(DIM / 128, MROWS / 128, 1);
    gemm_h<false><<<gOut, 256, G_SMEM>>>(Oh, Wh, nullptr, nullptr, nullptr, out, bo, nullptr, nullptr);
}